// round 5
// baseline (speedup 1.0000x reference)
#include <cuda_runtime.h>

#define DENSE_L   1024
#define NUM_G     16          // 16 groups of 4 k-values = 64 outputs/row
#define WIN       160         // window width per group (covers +-48 around every k in group)
#define ROWS      32          // rows per CTA tile
#define XS_STRIDE 1044        // smem row stride in floats: conflict-free lane-per-row LDS.128
#define NTHREADS  512
#define WG_ELEMS  (NUM_G * WIN * 4)   // 10240 floats

// Windowed W table, l-pair transposed: [g][jp][kk][parity], jp = l_off/2
__device__ float g_Wt[WG_ELEMS];

__device__ __forceinline__ int group_base(float w0, float w3) {
    float c = 0.5f * (w0 + w3);
    int bi = ((int)floorf(c) - 80) & ~3;   // align down to 4
    bi = bi < 0 ? 0 : bi;
    bi = bi > (DENSE_L - WIN) ? (DENSE_L - WIN) : bi;
    return bi;
}

__global__ void precompute_kernel(const float* __restrict__ weight) {
    int idx = blockIdx.x * blockDim.x + threadIdx.x;
    if (idx >= WG_ELEMS) return;
    int par = idx & 1;
    int kk  = (idx >> 1) & 3;
    int jp  = (idx >> 3) % (WIN / 2);
    int g   = idx / (WIN * 4);
    int base = group_base(weight[g * 4], weight[g * 4 + 3]);
    int l = base + jp * 2 + par;                 // l index into x row
    float d = (float)(l + 1) - weight[g * 4 + kk];   // t = l+1
    g_Wt[idx] = expf(-d * d * 0.01f);
}

__device__ __forceinline__ void fma2(unsigned long long &a,
                                     unsigned long long xp,
                                     unsigned long long wp) {
    asm("fma.rn.f32x2 %0, %1, %2, %0;" : "+l"(a) : "l"(xp), "l"(wp));
}

extern __shared__ float smem_dyn[];

__global__ __launch_bounds__(NTHREADS, 1)
void sampling_kernel(const float* __restrict__ x,
                     const float* __restrict__ weight,
                     float* __restrict__ out) {
    float* xs  = smem_dyn;                         // [ROWS][XS_STRIDE]
    float* wgs = smem_dyn + ROWS * XS_STRIDE;      // [WG_ELEMS]
    int tid = threadIdx.x;
    long long row0 = (long long)blockIdx.x * ROWS;

    // Stage W table (L2-resident after first CTAs)
    #pragma unroll
    for (int i = tid; i < WG_ELEMS; i += NTHREADS) wgs[i] = g_Wt[i];

    // Stage x tile: 32 consecutive rows = one contiguous 128KB chunk, float4 coalesced
    const float4* xg = (const float4*)(x + row0 * DENSE_L);
    #pragma unroll
    for (int i = 0; i < (ROWS * DENSE_L / 4) / NTHREADS; i++) {
        int idx = tid + i * NTHREADS;
        int r  = idx >> 8;          // /256 float4 per row
        int c4 = idx & 255;
        *(float4*)&xs[r * XS_STRIDE + (c4 << 2)] = xg[idx];
    }
    __syncthreads();

    int g    = tid >> 5;            // warp = k-group
    int lane = tid & 31;            // lane = row within tile
    int base = group_base(weight[g * 4], weight[g * 4 + 3]);  // identical fp math as precompute
    const float* xrow = xs + lane * XS_STRIDE + base;
    const float* wgp  = wgs + g * (WIN * 4);

    // Packed accumulators: (even-l partial, odd-l partial) per k
    unsigned long long acc0 = 0ull, acc1 = 0ull, acc2 = 0ull, acc3 = 0ull;

    #pragma unroll 8
    for (int j = 0; j < WIN; j += 4) {
        ulonglong2 xv = *(const ulonglong2*)(xrow + j);        // (x_j,x_j+1),(x_j+2,x_j+3)
        const ulonglong2* wq = (const ulonglong2*)(wgp + j * 4);
        ulonglong2 wA = wq[0];   // l=j,j+1 : k0 pair, k1 pair
        ulonglong2 wB = wq[1];   // l=j,j+1 : k2 pair, k3 pair
        fma2(acc0, xv.x, wA.x);
        fma2(acc1, xv.x, wA.y);
        fma2(acc2, xv.x, wB.x);
        fma2(acc3, xv.x, wB.y);
        ulonglong2 wC = wq[2];   // l=j+2,j+3 : k0,k1
        ulonglong2 wD = wq[3];   // l=j+2,j+3 : k2,k3
        fma2(acc0, xv.y, wC.x);
        fma2(acc1, xv.y, wC.y);
        fma2(acc2, xv.y, wD.x);
        fma2(acc3, xv.y, wD.y);
    }

    float2 a0 = *(float2*)&acc0;
    float2 a1 = *(float2*)&acc1;
    float2 a2 = *(float2*)&acc2;
    float2 a3 = *(float2*)&acc3;
    float4 res = make_float4(a0.x + a0.y, a1.x + a1.y, a2.x + a2.y, a3.x + a3.y);
    *(float4*)&out[(row0 + lane) * 64 + g * 4] = res;
}

extern "C" void kernel_launch(void* const* d_in, const int* in_sizes, int n_in,
                              void* d_out, int out_size) {
    const float* x      = (const float*)d_in[0];
    const float* weight = (const float*)d_in[1];
    float* out = (float*)d_out;
    int R = in_sizes[0] / DENSE_L;   // 131072 rows (B * NUM_ADC_P)

    size_t smem = (size_t)(ROWS * XS_STRIDE + WG_ELEMS) * sizeof(float);  // 174592 B
    cudaFuncSetAttribute((const void*)sampling_kernel,
                         cudaFuncAttributeMaxDynamicSharedMemorySize, (int)smem);

    precompute_kernel<<<(WG_ELEMS + 255) / 256, 256>>>(weight);
    sampling_kernel<<<R / ROWS, NTHREADS, smem>>>(x, weight, out);
}

// round 6
// speedup vs baseline: 1.3340x; 1.3340x over previous
#include <cuda_runtime.h>

#define DENSE_L   1024
#define NUM_G     16
#define WIN       160
#define JB        (WIN / 8)            // 20 j-blocks of 8 l each
#define RB        16                   // rows per buffer
#define XS_STRIDE 1032                 // smem row stride (floats); lane->chunk = 2*row+sub mod 8 (conflict-free)
#define NTHREADS  512
#define WG_ELEMS  (NUM_G * JB * 2 * 16)   // 10240 floats = 40KB

// W table layout: [g][jb][sub][jp2][kk][par]  (16 floats per (g,jb,sub) block)
__device__ float g_Wt[WG_ELEMS];

__device__ __forceinline__ int group_base(float w0, float w3) {
    float c = 0.5f * (w0 + w3);
    int bi = ((int)floorf(c) - 80) & ~3;
    bi = bi < 0 ? 0 : bi;
    bi = bi > (DENSE_L - WIN) ? (DENSE_L - WIN) : bi;
    return bi;
}

__global__ void precompute_kernel(const float* __restrict__ weight) {
    int idx = blockIdx.x * blockDim.x + threadIdx.x;
    if (idx >= WG_ELEMS) return;
    int par = idx & 1;
    int kk  = (idx >> 1) & 3;
    int jp2 = (idx >> 3) & 1;
    int sub = (idx >> 4) & 1;
    int jb  = (idx >> 5) % JB;
    int g   = idx / (JB * 32);
    int base = group_base(weight[g * 4], weight[g * 4 + 3]);
    int l = base + jb * 8 + sub * 4 + jp2 * 2 + par;
    float d = (float)(l + 1) - weight[g * 4 + kk];
    g_Wt[idx] = expf(-d * d * 0.01f);
}

__device__ __forceinline__ void fma2(unsigned long long &a,
                                     unsigned long long xp,
                                     unsigned long long wp) {
    asm("fma.rn.f32x2 %0, %1, %2, %0;" : "+l"(a) : "l"(xp), "l"(wp));
}

__device__ __forceinline__ void cp16(void* dst_smem, const void* src_gmem) {
    unsigned int d = (unsigned int)__cvta_generic_to_shared(dst_smem);
    asm volatile("cp.async.cg.shared.global [%0], [%1], 16;\n" :: "r"(d), "l"(src_gmem));
}
__device__ __forceinline__ void cp_commit() {
    asm volatile("cp.async.commit_group;\n");
}
__device__ __forceinline__ void cp_wait1() {
    asm volatile("cp.async.wait_group 1;\n" ::: "memory");
}
__device__ __forceinline__ void cp_wait0() {
    asm volatile("cp.async.wait_group 0;\n" ::: "memory");
}

__device__ __forceinline__ void stage_tile(float* xb, const float* __restrict__ xg, int tid) {
    // 16 rows * 256 float4 = 4096 cp.async of 16B; 8 per thread, coalesced per warp
    #pragma unroll
    for (int i = 0; i < (RB * DENSE_L / 4) / NTHREADS; i++) {
        int idx = tid + i * NTHREADS;
        int r   = idx >> 8;          // /256 float4 per row
        int c4  = idx & 255;
        cp16(&xb[r * XS_STRIDE + (c4 << 2)], &xg[(size_t)idx << 2]);
    }
}

extern __shared__ float smem_dyn[];

__global__ __launch_bounds__(NTHREADS, 1)
void sampling_kernel(const float* __restrict__ x,
                     const float* __restrict__ weight,
                     float* __restrict__ out,
                     int ntiles) {
    float* xs0 = smem_dyn;
    float* xs1 = smem_dyn + RB * XS_STRIDE;
    float* wgs = smem_dyn + 2 * RB * XS_STRIDE;
    int tid = threadIdx.x;

    // Stage W table once per CTA (L2-resident)
    #pragma unroll
    for (int i = tid; i < WG_ELEMS; i += NTHREADS) wgs[i] = g_Wt[i];

    int g    = tid >> 5;             // warp = k-group
    int lane = tid & 31;
    int row  = lane >> 1;            // 16 rows
    int sub  = lane & 1;             // window 4-float sub-slot
    int base = group_base(weight[g * 4], weight[g * 4 + 3]);  // same fp math as precompute

    const int G = gridDim.x;
    int t = blockIdx.x;

    // Prologue prefetch
    if (t < ntiles) stage_tile(xs0, x + (long long)t * RB * DENSE_L, tid);
    cp_commit();

    int cur = 0;
    for (; t < ntiles; t += G) {
        int tn = t + G;
        if (tn < ntiles) {
            stage_tile(cur ? xs0 : xs1, x + (long long)tn * RB * DENSE_L, tid);
            cp_commit();
            cp_wait1();              // current tile complete (groups retire in order)
        } else {
            cp_wait0();
        }
        __syncthreads();

        const float* xb   = cur ? xs1 : xs0;
        const float* xrow = xb + row * XS_STRIDE + base + sub * 4;
        const float* wp   = wgs + ((g * JB) * 2 + sub) * 16;

        unsigned long long acc0 = 0ull, acc1 = 0ull, acc2 = 0ull, acc3 = 0ull;
        #pragma unroll
        for (int jb = 0; jb < JB; jb++) {
            ulonglong2 xv = *(const ulonglong2*)(xrow + jb * 8);     // 4 floats for this sub
            const ulonglong2* wq = (const ulonglong2*)(wp + jb * 32);
            ulonglong2 wA = wq[0];   // jp2=0: k0 pair, k1 pair
            ulonglong2 wB = wq[1];   // jp2=0: k2 pair, k3 pair
            fma2(acc0, xv.x, wA.x);
            fma2(acc1, xv.x, wA.y);
            fma2(acc2, xv.x, wB.x);
            fma2(acc3, xv.x, wB.y);
            ulonglong2 wC = wq[2];   // jp2=1: k0, k1
            ulonglong2 wD = wq[3];   // jp2=1: k2, k3
            fma2(acc0, xv.y, wC.x);
            fma2(acc1, xv.y, wC.y);
            fma2(acc2, xv.y, wD.x);
            fma2(acc3, xv.y, wD.y);
        }

        // Combine the two sub-halves of each row (lanes 2r / 2r+1)
        unsigned long long o0 = __shfl_xor_sync(0xffffffffu, acc0, 1);
        unsigned long long o1 = __shfl_xor_sync(0xffffffffu, acc1, 1);
        unsigned long long o2 = __shfl_xor_sync(0xffffffffu, acc2, 1);
        unsigned long long o3 = __shfl_xor_sync(0xffffffffu, acc3, 1);
        float2 a0 = *(float2*)&acc0, b0 = *(float2*)&o0;
        float2 a1 = *(float2*)&acc1, b1 = *(float2*)&o1;
        float2 a2 = *(float2*)&acc2, b2 = *(float2*)&o2;
        float2 a3 = *(float2*)&acc3, b3 = *(float2*)&o3;
        if (sub == 0) {
            float4 res = make_float4(a0.x + a0.y + b0.x + b0.y,
                                     a1.x + a1.y + b1.x + b1.y,
                                     a2.x + a2.y + b2.x + b2.y,
                                     a3.x + a3.y + b3.x + b3.y);
            *(float4*)&out[((long long)t * RB + row) * 64 + g * 4] = res;
        }
        __syncthreads();             // tile fully consumed before it is restaged
        cur ^= 1;
    }
}

extern "C" void kernel_launch(void* const* d_in, const int* in_sizes, int n_in,
                              void* d_out, int out_size) {
    const float* x      = (const float*)d_in[0];
    const float* weight = (const float*)d_in[1];
    float* out = (float*)d_out;
    int R = in_sizes[0] / DENSE_L;       // total rows (B * NUM_ADC_P)
    int ntiles = R / RB;                 // 8192

    size_t smem = (size_t)(2 * RB * XS_STRIDE + WG_ELEMS) * sizeof(float);  // 173056 B
    cudaFuncSetAttribute((const void*)sampling_kernel,
                         cudaFuncAttributeMaxDynamicSharedMemorySize, (int)smem);

    int sms = 148;
    cudaDeviceGetAttribute(&sms, cudaDevAttrMultiProcessorCount, 0);

    precompute_kernel<<<(WG_ELEMS + 255) / 256, 256>>>(weight);
    sampling_kernel<<<sms, NTHREADS, smem>>>(x, weight, out, ntiles);
}